// round 16
// baseline (speedup 1.0000x reference)
#include <cuda_runtime.h>
#include <cuda_bf16.h>

#define FEAT      4096
#define NTHREADS  256
#define PER       16          // FEAT / NTHREADS
#define SEL_RANK  2048u
#define SLOT_CAP  16
#define NBINS     128         // interval bins over [-0.125, 0.125), width 1/512
#define F_LIM     0.125f

// monotone fp32 -> u32 key (fallback path only)
__device__ __forceinline__ unsigned int fkey(float f) {
    unsigned int u = __float_as_uint(f);
    return u ^ ((unsigned int)((int)u >> 31) | 0x80000000u);
}
__device__ __forceinline__ float kinv(unsigned int k) {
    unsigned int m = (unsigned int)((int)(~k) >> 31) | 0x80000000u;
    return __uint_as_float(k ^ m);
}

// Warp-collective scan of a 128-bin shared histogram (4 bins/lane): find the
// bin containing `rank`; broadcast to all lanes. {0xFFFFFFFF,0} if not found.
__device__ __forceinline__ uint2 warp_select128(const unsigned int* hist, unsigned int rank)
{
    const unsigned int lane = threadIdx.x & 31;
    uint4 a = reinterpret_cast<const uint4*>(hist)[lane];
    unsigned int csum = a.x + a.y + a.z + a.w;
    unsigned int v = csum;
    #pragma unroll
    for (int off = 1; off < 32; off <<= 1) {
        unsigned int t = __shfl_up_sync(0xFFFFFFFFu, v, off);
        if (lane >= (unsigned)off) v += t;
    }
    const unsigned int base = v - csum;
    const bool found = (rank - base) < csum;   // unsigned in-range trick
    unsigned int d = 0, r = 0;
    if (found) {
        r = rank - base;
        d = lane * 4u;
        if (r >= a.x) { r -= a.x; d++;
            if (r >= a.y) { r -= a.y; d++;
                if (r >= a.z) { r -= a.z; d++; } } }
    }
    const unsigned int m = __ballot_sync(0xFFFFFFFFu, found);
    if (m == 0u) return make_uint2(0xFFFFFFFFu, 0u);
    const int src = __ffs(m) - 1;
    d = __shfl_sync(0xFFFFFFFFu, d, src);
    r = __shfl_sync(0xFFFFFFFFu, r, src);
    return make_uint2(d, r);
}

// 256-bin variant for the exact fallback path.
__device__ __forceinline__ uint2 warp_select256(const unsigned int* hist, unsigned int rank)
{
    const unsigned int lane = threadIdx.x & 31;
    uint4 a = reinterpret_cast<const uint4*>(hist)[2 * lane];
    uint4 b = reinterpret_cast<const uint4*>(hist)[2 * lane + 1];
    unsigned int c[8] = {a.x, a.y, a.z, a.w, b.x, b.y, b.z, b.w};
    unsigned int csum = c[0]+c[1]+c[2]+c[3]+c[4]+c[5]+c[6]+c[7];
    unsigned int v = csum;
    #pragma unroll
    for (int off = 1; off < 32; off <<= 1) {
        unsigned int t = __shfl_up_sync(0xFFFFFFFFu, v, off);
        if (lane >= (unsigned)off) v += t;
    }
    const unsigned int base = v - csum;
    const bool found = (rank - base) < csum;
    unsigned int d = 0, r = 0;
    if (found) {
        r = rank - base;
        d = lane * 8u;
        #pragma unroll
        for (int i = 0; i < 7; i++) {
            if (r >= c[i]) { r -= c[i]; d++; }
            else break;
        }
    }
    const unsigned int m = __ballot_sync(0xFFFFFFFFu, found);
    if (m == 0u) return make_uint2(0xFFFFFFFFu, 0u);
    const int src = __ffs(m) - 1;
    d = __shfl_sync(0xFFFFFFFFu, d, src);
    r = __shfl_sync(0xFFFFFFFFu, r, src);
    return make_uint2(d, r);
}

__global__ __launch_bounds__(NTHREADS, 8)
void MaxoutDynamic_kernel(const float* __restrict__ feat, float* __restrict__ out) {
    __shared__ __align__(16) unsigned int hist[256];            // fast path uses [0,128)
    __shared__ __align__(16) float slots[NBINS * SLOT_CAP];     // 8 KB
    __shared__ unsigned int wsum[8];
    __shared__ unsigned int s_state;
    __shared__ float s_T;

    const int tid = threadIdx.x;
    const unsigned int lane = tid & 31;
    const unsigned int wid  = tid >> 5;
    const size_t row_off = (size_t)blockIdx.x * FEAT;

    // ---- load row (4 x LDG.128, streaming: read exactly once) ----
    const float4* in4 = reinterpret_cast<const float4*>(feat + row_off);
    float4 v0 = __ldcs(in4 + tid);
    float4 v1 = __ldcs(in4 + tid + NTHREADS);
    float4 v2 = __ldcs(in4 + tid + 2 * NTHREADS);
    float4 v3 = __ldcs(in4 + tid + 3 * NTHREADS);

    if (tid < 32) reinterpret_cast<uint4*>(hist)[tid] = make_uint4(0u,0u,0u,0u);
    __syncthreads();   // B1: hist zeroed before atomics

    float f[PER] = {v0.x, v0.y, v0.z, v0.w, v1.x, v1.y, v1.z, v1.w,
                    v2.x, v2.y, v2.z, v2.w, v3.x, v3.y, v3.z, v3.w};

    float4* out4 = reinterpret_cast<float4*>(out + row_off);

    // ---- ONE pass per 4-elem group: filter, bin rare elems, and EARLY-STORE
    //      groups with no interval element (valid whenever T lands in the
    //      interval — i.e. the fast path; fallback rewrites everything) ----
    // interval = [-0.125, 0.125]; row-median threshold ~N(0,0.02): 6+ sigma
    unsigned int below = 0;
    unsigned int pend = 0;     // bitmask: group j needs T
    #pragma unroll
    for (int j = 0; j < 4; j++) {
        bool u0 = fabsf(f[4*j+0]) <= F_LIM;
        bool u1 = fabsf(f[4*j+1]) <= F_LIM;
        bool u2 = fabsf(f[4*j+2]) <= F_LIM;
        bool u3 = fabsf(f[4*j+3]) <= F_LIM;
        below += (f[4*j+0] < -F_LIM) + (f[4*j+1] < -F_LIM)
               + (f[4*j+2] < -F_LIM) + (f[4*j+3] < -F_LIM);
        #pragma unroll
        for (int e = 4*j; e < 4*j+4; e++) {
            if (fabsf(f[e]) <= F_LIM) {   // rare (~1.6/16)
                int b = __float2int_rd(fmaf(f[e], 512.0f, 64.0f));
                if ((unsigned int)b < (unsigned)NBINS) {   // f==+0.125 edge
                    unsigned int old = atomicAdd(&hist[b], 1u);
                    if (old < SLOT_CAP) slots[b * SLOT_CAP + old] = f[e];
                }
            }
        }
        if (u0 | u1 | u2 | u3) {
            pend |= 1u << j;
        } else {
            // all four strictly outside: f > F_LIM => keep, f < -F_LIM => zero
            float4 r;
            r.x = (f[4*j+0] > F_LIM) ? 2.0f * f[4*j+0] : 0.0f;
            r.y = (f[4*j+1] > F_LIM) ? 2.0f * f[4*j+1] : 0.0f;
            r.z = (f[4*j+2] > F_LIM) ? 2.0f * f[4*j+2] : 0.0f;
            r.w = (f[4*j+3] > F_LIM) ? 2.0f * f[4*j+3] : 0.0f;
            __stcs(out4 + tid + j * NTHREADS, r);   // overlaps select phase
        }
    }
    below = __reduce_add_sync(0xFFFFFFFFu, below);
    if (lane == 0) wsum[wid] = below;
    __syncthreads();   // B2: hist/slots/wsum frozen

    // ---- warp 0 alone selects the threshold ----
    if (wid == 0) {
        const unsigned int tot =
            __reduce_add_sync(0xFFFFFFFFu, (lane < 8u) ? wsum[lane] : 0u);
        const uint2 sr = warp_select128(hist, SEL_RANK - tot);   // rank may wrap

        bool bad = (sr.x == 0xFFFFFFFFu);
        unsigned int cnt = 0;
        if (!bad) {
            cnt = hist[sr.x];
            bad = (cnt > SLOT_CAP);   // selected-bin overflow (rare)
        }
        if (!bad) {
            float fi = (lane < cnt) ? slots[sr.x * SLOT_CAP + lane] : 0.0f;
            unsigned int cl = 0;
            for (unsigned int j = 0; j < cnt; j++) {
                float fj = __shfl_sync(0xFFFFFFFFu, fi, j);
                cl += (fj < fi) || (fj == fi && j < lane);
            }
            const unsigned int wm =
                __ballot_sync(0xFFFFFFFFu, (lane < cnt) && (cl == sr.y));
            float tw = __shfl_sync(0xFFFFFFFFu, fi, __ffs(wm) - 1);
            if (lane == 0) { s_T = tw; s_state = 0u; }
        } else {
            if (lane == 0) s_state = 1u;
        }
    }
    __syncthreads();   // B3: s_T / s_state published

    if (s_state == 0u) {
        const float T = s_T;   // T in [-0.125, 0.125): early stores were valid
        #pragma unroll
        for (int j = 0; j < 4; j++) {
            if (pend & (1u << j)) {
                float4 r;
                r.x = (f[4*j+0] >= T) ? 2.0f * f[4*j+0] : 0.0f;
                r.y = (f[4*j+1] >= T) ? 2.0f * f[4*j+1] : 0.0f;
                r.z = (f[4*j+2] >= T) ? 2.0f * f[4*j+2] : 0.0f;
                r.w = (f[4*j+3] >= T) ? 2.0f * f[4*j+3] : 0.0f;
                __stcs(out4 + tid + j * NTHREADS, r);
            }
        }
    } else {
        // ---- general exact fallback (block-uniform, rare):
        //      4-pass 8-bit MSB radix select; rewrites ALL groups ----
        unsigned int key[PER];
        #pragma unroll
        for (int e = 0; e < PER; e++) key[e] = fkey(f[e]);
        unsigned int prefix = 0u, pmask = 0u, rnk = SEL_RANK;
        for (int p = 0; p < 4; p++) {
            const int shift = 24 - 8 * p;
            __syncthreads();
            if (tid < 64) reinterpret_cast<uint4*>(hist)[tid] = make_uint4(0u,0u,0u,0u);
            __syncthreads();
            #pragma unroll
            for (int e = 0; e < PER; e++)
                if ((key[e] & pmask) == prefix)
                    atomicAdd(&hist[(key[e] >> shift) & 255u], 1u);
            __syncthreads();
            const uint2 pr = warp_select256(hist, rnk);   // redundant per warp
            prefix |= pr.x << shift;
            pmask  |= 255u << shift;
            rnk = pr.y;
        }
        const float T = kinv(prefix);
        #pragma unroll
        for (int j = 0; j < 4; j++) {
            float4 r;
            r.x = (f[4*j+0] >= T) ? 2.0f * f[4*j+0] : 0.0f;
            r.y = (f[4*j+1] >= T) ? 2.0f * f[4*j+1] : 0.0f;
            r.z = (f[4*j+2] >= T) ? 2.0f * f[4*j+2] : 0.0f;
            r.w = (f[4*j+3] >= T) ? 2.0f * f[4*j+3] : 0.0f;
            __stcs(out4 + tid + j * NTHREADS, r);   // overwrites early stores
        }
    }
}

extern "C" void kernel_launch(void* const* d_in, const int* in_sizes, int n_in,
                              void* d_out, int out_size) {
    const float* feat = (const float*)d_in[0];
    float* out = (float*)d_out;
    const int rows = in_sizes[0] / FEAT;   // 16384
    MaxoutDynamic_kernel<<<rows, NTHREADS>>>(feat, out);
}

// round 17
// speedup vs baseline: 1.0647x; 1.0647x over previous
#include <cuda_runtime.h>
#include <cuda_bf16.h>

#define FEAT      4096
#define NTHREADS  256
#define PER       16          // FEAT / NTHREADS
#define SEL_RANK  2048u
#define SLOT_CAP  16
#define NBINS     128         // bins over [-0.125, 0.125), width 1/512
#define F_LIM     0.09375f    // candidate filter (narrower than bin range; 4.8 sigma)

// monotone fp32 -> u32 key (fallback path only)
__device__ __forceinline__ unsigned int fkey(float f) {
    unsigned int u = __float_as_uint(f);
    return u ^ ((unsigned int)((int)u >> 31) | 0x80000000u);
}
__device__ __forceinline__ float kinv(unsigned int k) {
    unsigned int m = (unsigned int)((int)(~k) >> 31) | 0x80000000u;
    return __uint_as_float(k ^ m);
}

// Warp-collective scan of a 128-bin shared histogram (4 bins/lane): find the
// bin containing `rank`; broadcast to all lanes. {0xFFFFFFFF,0} if not found.
__device__ __forceinline__ uint2 warp_select128(const unsigned int* hist, unsigned int rank)
{
    const unsigned int lane = threadIdx.x & 31;
    uint4 a = reinterpret_cast<const uint4*>(hist)[lane];
    unsigned int csum = a.x + a.y + a.z + a.w;
    unsigned int v = csum;
    #pragma unroll
    for (int off = 1; off < 32; off <<= 1) {
        unsigned int t = __shfl_up_sync(0xFFFFFFFFu, v, off);
        if (lane >= (unsigned)off) v += t;
    }
    const unsigned int base = v - csum;
    const bool found = (rank - base) < csum;   // unsigned in-range trick
    unsigned int d = 0, r = 0;
    if (found) {
        r = rank - base;
        d = lane * 4u;
        if (r >= a.x) { r -= a.x; d++;
            if (r >= a.y) { r -= a.y; d++;
                if (r >= a.z) { r -= a.z; d++; } } }
    }
    const unsigned int m = __ballot_sync(0xFFFFFFFFu, found);
    if (m == 0u) return make_uint2(0xFFFFFFFFu, 0u);
    const int src = __ffs(m) - 1;
    d = __shfl_sync(0xFFFFFFFFu, d, src);
    r = __shfl_sync(0xFFFFFFFFu, r, src);
    return make_uint2(d, r);
}

// 256-bin variant for the exact fallback path.
__device__ __forceinline__ uint2 warp_select256(const unsigned int* hist, unsigned int rank)
{
    const unsigned int lane = threadIdx.x & 31;
    uint4 a = reinterpret_cast<const uint4*>(hist)[2 * lane];
    uint4 b = reinterpret_cast<const uint4*>(hist)[2 * lane + 1];
    unsigned int c[8] = {a.x, a.y, a.z, a.w, b.x, b.y, b.z, b.w};
    unsigned int csum = c[0]+c[1]+c[2]+c[3]+c[4]+c[5]+c[6]+c[7];
    unsigned int v = csum;
    #pragma unroll
    for (int off = 1; off < 32; off <<= 1) {
        unsigned int t = __shfl_up_sync(0xFFFFFFFFu, v, off);
        if (lane >= (unsigned)off) v += t;
    }
    const unsigned int base = v - csum;
    const bool found = (rank - base) < csum;
    unsigned int d = 0, r = 0;
    if (found) {
        r = rank - base;
        d = lane * 8u;
        #pragma unroll
        for (int i = 0; i < 7; i++) {
            if (r >= c[i]) { r -= c[i]; d++; }
            else break;
        }
    }
    const unsigned int m = __ballot_sync(0xFFFFFFFFu, found);
    if (m == 0u) return make_uint2(0xFFFFFFFFu, 0u);
    const int src = __ffs(m) - 1;
    d = __shfl_sync(0xFFFFFFFFu, d, src);
    r = __shfl_sync(0xFFFFFFFFu, r, src);
    return make_uint2(d, r);
}

__global__ __launch_bounds__(NTHREADS, 8)
void MaxoutDynamic_kernel(const float* __restrict__ feat, float* __restrict__ out) {
    __shared__ __align__(16) unsigned int hist[256];            // fast path uses [0,128)
    __shared__ __align__(16) float slots[NBINS * SLOT_CAP];     // 8 KB
    __shared__ unsigned int wsum[8];

    const int tid = threadIdx.x;
    const unsigned int lane = tid & 31;
    const unsigned int wid  = tid >> 5;
    const size_t row_off = (size_t)blockIdx.x * FEAT;

    // ---- load row (4 x LDG.128, streaming / evict-first: read exactly once) ----
    const float4* in4 = reinterpret_cast<const float4*>(feat + row_off);
    float4 v0 = __ldcs(in4 + tid);
    float4 v1 = __ldcs(in4 + tid + NTHREADS);
    float4 v2 = __ldcs(in4 + tid + 2 * NTHREADS);
    float4 v3 = __ldcs(in4 + tid + 3 * NTHREADS);

    if (tid < 32) reinterpret_cast<uint4*>(hist)[tid] = make_uint4(0u,0u,0u,0u);
    __syncthreads();   // B1: hist zeroed before atomics

    float f[PER] = {v0.x, v0.y, v0.z, v0.w, v1.x, v1.y, v1.z, v1.w,
                    v2.x, v2.y, v2.z, v2.w, v3.x, v3.y, v3.z, v3.w};

    // ---- ONE pass: cheap float-compare filter; bin math only for ~1.2/16 elems ----
    // candidate interval = [-0.09375, 0.09375]; row-median threshold ~N(0,0.0196):
    // 4.8 sigma margin (expected fallback rows per launch ~0.03, handled exactly)
    unsigned int below = 0;
    #pragma unroll
    for (int e = 0; e < PER; e++) {
        below += (f[e] < -F_LIM);                       // FSETP + pred IADD
        if (fabsf(f[e]) <= F_LIM) {                     // FSETP (|.| free)
            int b = __float2int_rd(fmaf(f[e], 512.0f, 64.0f));   // rare path
            if ((unsigned int)b < (unsigned)NBINS) {
                unsigned int old = atomicAdd(&hist[b], 1u);
                if (old < SLOT_CAP) slots[b * SLOT_CAP + old] = f[e];
            }
        }
    }
    below = __reduce_add_sync(0xFFFFFFFFu, below);
    if (lane == 0) wsum[wid] = below;
    __syncthreads();   // B2: hist/slots/wsum frozen — last barrier on fast path

    // ---- EVERY warp redundantly selects the threshold (identical result,
    //      no third barrier; waiting warps would cost the same anyway) ----
    const unsigned int tot =
        __reduce_add_sync(0xFFFFFFFFu, (lane < 8u) ? wsum[lane] : 0u);
    const uint2 sr = warp_select128(hist, SEL_RANK - tot);   // rank may wrap

    bool bad = (sr.x == 0xFFFFFFFFu);
    unsigned int cnt = 0;
    if (!bad) {
        cnt = hist[sr.x];
        bad = (cnt > SLOT_CAP);   // selected-bin overflow (rare)
    }
    // `bad` is block-uniform: derived only from frozen shared data.

    float T;
    if (!bad) {
        // rank the <=16 slot floats of the selected bin within each warp
        float fi = (lane < cnt) ? slots[sr.x * SLOT_CAP + lane] : 0.0f;
        unsigned int cl = 0;
        for (unsigned int j = 0; j < cnt; j++) {
            float fj = __shfl_sync(0xFFFFFFFFu, fi, j);
            cl += (fj < fi) || (fj == fi && j < lane);
        }
        const unsigned int wm = __ballot_sync(0xFFFFFFFFu, (lane < cnt) && (cl == sr.y));
        T = __shfl_sync(0xFFFFFFFFu, fi, __ffs(wm) - 1);   // exactly one winner
    } else {
        // ---- general exact fallback (block-uniform, rare):
        //      4-pass 8-bit MSB radix select over monotone keys ----
        unsigned int key[PER];
        #pragma unroll
        for (int e = 0; e < PER; e++) key[e] = fkey(f[e]);
        unsigned int prefix = 0u, pmask = 0u, rnk = SEL_RANK;
        for (int p = 0; p < 4; p++) {
            const int shift = 24 - 8 * p;
            __syncthreads();
            if (tid < 64) reinterpret_cast<uint4*>(hist)[tid] = make_uint4(0u,0u,0u,0u);
            __syncthreads();
            #pragma unroll
            for (int e = 0; e < PER; e++)
                if ((key[e] & pmask) == prefix)
                    atomicAdd(&hist[(key[e] >> shift) & 255u], 1u);
            __syncthreads();
            const uint2 pr = warp_select256(hist, rnk);   // redundant per warp
            prefix |= pr.x << shift;
            pmask  |= 255u << shift;
            rnk = pr.y;
        }
        T = kinv(prefix);
    }

    // ---- predicated scaled writeback (streaming stores) ----
    float4* out4 = reinterpret_cast<float4*>(out + row_off);
    #pragma unroll
    for (int j = 0; j < 4; j++) {
        float4 r;
        r.x = (f[4*j+0] >= T) ? 2.0f * f[4*j+0] : 0.0f;
        r.y = (f[4*j+1] >= T) ? 2.0f * f[4*j+1] : 0.0f;
        r.z = (f[4*j+2] >= T) ? 2.0f * f[4*j+2] : 0.0f;
        r.w = (f[4*j+3] >= T) ? 2.0f * f[4*j+3] : 0.0f;
        __stcs(out4 + tid + j * NTHREADS, r);
    }
}

extern "C" void kernel_launch(void* const* d_in, const int* in_sizes, int n_in,
                              void* d_out, int out_size) {
    const float* feat = (const float*)d_in[0];
    float* out = (float*)d_out;
    const int rows = in_sizes[0] / FEAT;   // 16384
    MaxoutDynamic_kernel<<<rows, NTHREADS>>>(feat, out);
}